// round 13
// baseline (speedup 1.0000x reference)
#include <cuda_runtime.h>
#include <math.h>
#include <string.h>

#define LEN   2048
#define BATCH 64
#define NH    8
#define SCH   64          // flash chunk (rows per CTA)
#define NSC   32          // # chunks

#define FFMA2(acc, x, y) \
    asm("fma.rn.f32x2 %0, %1, %2, %0;" : "+l"(acc) : "l"(x), "l"(y))
#define PACK2(out, lo, hi) \
    asm("mov.b64 %0, {%1, %2};" : "=l"(out) : "f"(lo), "f"(hi))
#define UNPACK2(lo, hi, in) \
    asm("mov.b64 {%0, %1}, %2;" : "=f"(lo), "=f"(hi) : "l"(in))

// ---------------- scratch (device globals; no allocation) ----------------
__device__ float g_q[BATCH * 2048];              // q[b][h*256+k]
__device__ float g_mc[NSC * BATCH * NH];         // chunk-local max
__device__ float g_sc[NSC * BATCH * NH];         // chunk-local sum-exp
__device__ float g_rpart[NSC * BATCH * 2048];    // UNNORMALIZED chunk read partials
__device__ float g_opart[64 * BATCH * 256];      // kc partials of out

// ---------------- K1: q GEMM: q = query@Wq + bq (3-way j split) -----------
__global__ void __launch_bounds__(256) k_qgemm(const float* __restrict__ query,
                                               const float* __restrict__ Wq,
                                               const float* __restrict__ bq,
                                               int jt_off) {
    __shared__ float w_s[32][10];    // [k][j] pad
    __shared__ float q_s[64][33];    // [b][k] pad
    int jt = blockIdx.x + jt_off;
    int tid = threadIdx.x;
    int b = tid & 63, jg = tid >> 6;
    float acc0 = 0.f, acc1 = 0.f;
    for (int kt = 0; kt < 8; kt++) {
        {   // Wq tile 32k x 8j
            int k = tid >> 3, j = tid & 7;
            w_s[k][j] = Wq[(size_t)(kt * 32 + k) * 2048 + jt * 8 + j];
        }
#pragma unroll
        for (int it = 0; it < 2; it++) {   // query tile 64b x 32k, float4
            int f4 = tid + it * 256;
            int bb = f4 >> 3, k4 = f4 & 7;
            float4 v = ((const float4*)query)[bb * 64 + kt * 8 + k4];
            q_s[bb][k4 * 4 + 0] = v.x;
            q_s[bb][k4 * 4 + 1] = v.y;
            q_s[bb][k4 * 4 + 2] = v.z;
            q_s[bb][k4 * 4 + 3] = v.w;
        }
        __syncthreads();
#pragma unroll
        for (int kk = 0; kk < 32; kk++) {
            float qv = q_s[b][kk];
            acc0 += qv * w_s[kk][jg * 2 + 0];
            acc1 += qv * w_s[kk][jg * 2 + 1];
        }
        __syncthreads();
    }
    int j0 = jt * 8 + jg * 2;
    g_q[b * 2048 + j0 + 0] = acc0 + bq[j0 + 0];
    g_q[b * 2048 + j0 + 1] = acc1 + bq[j0 + 1];
}

// ---------------- K2: FUSED scores + chunk softmax + weighted read --------
// grid (32 cc, 64 b), 256 thr. Dead chunks exit with zero traffic.
__global__ void __launch_bounds__(256) k_flash(const float* __restrict__ keys,
                                               const float* __restrict__ vals,
                                               const float* __restrict__ rpe,
                                               const int* __restrict__ steps) {
    int c = blockIdx.x, b = blockIdx.y;
    int lbase = c * SCH;
    int n = steps[b];
    if (lbase >= n) return;
    int nv = n - lbase; if (nv > SCH) nv = SCH;
    int tid = threadIdx.x;

    __shared__ float ks[64][71];                 // keys k-tile, pad 71
    __shared__ unsigned long long q2[4 * 256];   // [hp][k] packed head-pair q
    __shared__ float r_s[SCH];
    __shared__ float s_s[8 * 68];                // scores [h][l]
    __shared__ float m_s[8];
    __shared__ __align__(16) unsigned long long w2[SCH * 4]; // splat weights [l][hp]

    // ---- build q2 (coalesced) ----
#pragma unroll
    for (int it = 0; it < 4; it++) {
        float lo = g_q[b * 2048 + (2 * it) * 256 + tid];
        float hi = g_q[b * 2048 + (2 * it + 1) * 256 + tid];
        unsigned long long p;
        PACK2(p, lo, hi);
        q2[it * 256 + tid] = p;
    }
    if (tid < SCH) r_s[tid] = rpe[(lbase + tid) * 64 + b];

    // ---- phase A: scores tile-GEMM (4 k-tiles, reg-prefetched) ----
    {
        float4 buf[4];
        int rowv[4], colv[4];
#pragma unroll
        for (int it = 0; it < 4; it++) {
            int f4 = tid + it * 256;
            int row = f4 >> 4;
            rowv[it] = (row < nv) ? row : (nv - 1);
            colv[it] = f4 & 15;
        }
#pragma unroll
        for (int it = 0; it < 4; it++)
            buf[it] = ((const float4*)keys)[((size_t)(lbase + rowv[it]) * 64 + b) * 64 + 0 * 16 + colv[it]];

        int hp = tid >> 6, l = tid & 63;
        unsigned long long acc = 0ull;

#pragma unroll
        for (int t = 0; t < 4; t++) {
#pragma unroll
            for (int it = 0; it < 4; it++) {
                int f4 = tid + it * 256;
                int row = f4 >> 4, col = colv[it];
                ks[row][col * 4 + 0] = buf[it].x;
                ks[row][col * 4 + 1] = buf[it].y;
                ks[row][col * 4 + 2] = buf[it].z;
                ks[row][col * 4 + 3] = buf[it].w;
            }
            __syncthreads();
            if (t < 3) {
#pragma unroll
                for (int it = 0; it < 4; it++)
                    buf[it] = ((const float4*)keys)[((size_t)(lbase + rowv[it]) * 64 + b) * 64 + (t + 1) * 16 + colv[it]];
            }
            const unsigned long long* qp = q2 + hp * 256 + t * 64;
            const float* kr = ks[l];
#pragma unroll
            for (int kk = 0; kk < 64; kk++) {
                float kv = kr[kk];
                unsigned long long vv;
                PACK2(vv, kv, kv);
                FFMA2(acc, vv, qp[kk]);
            }
            __syncthreads();
        }

        float lo, hi;
        UNPACK2(lo, hi, acc);
        float r = r_s[l];
        s_s[(2 * hp) * 68 + l]     = lo * r;
        s_s[(2 * hp + 1) * 68 + l] = hi * r;
    }
    __syncthreads();

    // ---- phase B: chunk-local stats + splat weight build ----
    {
        int h = tid >> 5, lane = tid & 31;
        float m = -3.0e38f;
        for (int ll = lane; ll < nv; ll += 32) m = fmaxf(m, s_s[h * 68 + ll]);
#pragma unroll
        for (int o = 16; o > 0; o >>= 1) m = fmaxf(m, __shfl_xor_sync(0xffffffffu, m, o));
        float s = 0.f;
        for (int ll = lane; ll < nv; ll += 32) s += __expf(s_s[h * 68 + ll] - m);
#pragma unroll
        for (int o = 16; o > 0; o >>= 1) s += __shfl_xor_sync(0xffffffffu, s, o);
        if (lane == 0) {
            g_mc[(c * 64 + b) * 8 + h] = m;
            g_sc[(c * 64 + b) * 8 + h] = s;
            m_s[h] = m;
        }
    }
    __syncthreads();
    {
        int l = tid & 63, hp = tid >> 6;
        float m0 = m_s[2 * hp], m1 = m_s[2 * hp + 1];
        float w0 = 0.f, w1 = 0.f;
        if (l < nv) {
            w0 = __expf(s_s[(2 * hp) * 68 + l] - m0);
            w1 = __expf(s_s[(2 * hp + 1) * 68 + l] - m1);
        }
        unsigned long long p;
        PACK2(p, w0, w1);
        w2[l * 4 + hp] = p;
    }
    __syncthreads();

    // ---- phase C: stream vals, unnormalized weighted accumulate ----
    unsigned long long ah[4];
#pragma unroll
    for (int i = 0; i < 4; i++) ah[i] = 0ull;
    const float* vp = vals + ((size_t)lbase * 64 + b) * 256 + tid;
    int l = 0;
    for (; l + 16 <= nv; l += 16) {
        float v[16];
#pragma unroll
        for (int i = 0; i < 16; i++) v[i] = vp[(size_t)(l + i) * 16384];
#pragma unroll
        for (int i = 0; i < 16; i++) {
            unsigned long long vv;
            PACK2(vv, v[i], v[i]);
#pragma unroll
            for (int hpp = 0; hpp < 4; hpp++)
                FFMA2(ah[hpp], w2[(l + i) * 4 + hpp], vv);
        }
    }
    for (; l < nv; l++) {
        float v = vp[(size_t)l * 16384];
        unsigned long long vv;
        PACK2(vv, v, v);
#pragma unroll
        for (int hpp = 0; hpp < 4; hpp++)
            FFMA2(ah[hpp], w2[l * 4 + hpp], vv);
    }
    size_t pbase = ((size_t)c * 64 + b) * 2048;
#pragma unroll
    for (int hpp = 0; hpp < 4; hpp++) {
        float lo, hi;
        UNPACK2(lo, hi, ah[hpp]);
        g_rpart[pbase + (hpp * 2 + 0) * 256 + tid] = lo;
        g_rpart[pbase + (hpp * 2 + 1) * 256 + tid] = hi;
    }
}

// ---------------- K3: out GEMM with fused softmax-merge, kc of 32 ---------
// grid (64 kc, 8 bt), 256 thr. head h = kc>>3 fixed per CTA.
__global__ void __launch_bounds__(256) k_outgemm(const float* __restrict__ Wa,
                                                 const int* __restrict__ steps) {
    int kc = blockIdx.x, bt = blockIdx.y;
    int h = kc >> 3;
    int tid = threadIdx.x;
    __shared__ __align__(16) float R_s[32 * 8];  // [k][bi]
    __shared__ float f_s[8][32];                 // merge factor [bi][cc]
    __shared__ int nc_s[8];

    {   // factors: warp w = bi, lanes = cc
        int bi = tid >> 5, cc = tid & 31;
        int b = bt * 8 + bi;
        int n = steps[b];
        int nc = (n + SCH - 1) >> 6;
        if (cc == 0) nc_s[bi] = nc;
        int valid = cc < nc;
        float m = valid ? g_mc[(cc * 64 + b) * 8 + h] : -3.0e38f;
        float s = valid ? g_sc[(cc * 64 + b) * 8 + h] : 0.f;
        float M = m;
#pragma unroll
        for (int o = 16; o > 0; o >>= 1) M = fmaxf(M, __shfl_xor_sync(0xffffffffu, M, o));
        float e = __expf(m - M);
        float denom = e * s;
#pragma unroll
        for (int o = 16; o > 0; o >>= 1) denom += __shfl_xor_sync(0xffffffffu, denom, o);
        f_s[bi][cc] = e / denom;
    }
    __syncthreads();

    {   // stage + fused 32-chunk weighted merge
        int bi = tid >> 5, k = tid & 31;
        int b = bt * 8 + bi;
        int nc = nc_s[bi];
        float s = 0.f;
#pragma unroll
        for (int cc = 0; cc < 32; cc++)
            if (cc < nc)
                s += f_s[bi][cc] * g_rpart[((size_t)cc * 64 + b) * 2048 + kc * 32 + k];
        R_s[k * 8 + bi] = s;
    }
    __syncthreads();

    unsigned long long acc[4];
#pragma unroll
    for (int p = 0; p < 4; p++) acc[p] = 0ull;
    const unsigned long long* R2 = (const unsigned long long*)R_s;
#pragma unroll 8
    for (int k = 0; k < 32; k++) {
        float wa = Wa[(size_t)(kc * 32 + k) * 256 + tid];
        unsigned long long wv;
        PACK2(wv, wa, wa);
#pragma unroll
        for (int p = 0; p < 4; p++)
            FFMA2(acc[p], R2[k * 4 + p], wv);
    }
#pragma unroll
    for (int p = 0; p < 4; p++) {
        float lo, hi;
        UNPACK2(lo, hi, acc[p]);
        g_opart[((size_t)kc * 64 + bt * 8 + 2 * p + 0) * 256 + tid] = lo;
        g_opart[((size_t)kc * 64 + bt * 8 + 2 * p + 1) * 256 + tid] = hi;
    }
}

// ---------------- K4: final reduce + bias (128 CTAs x 128 thr) ------------
__global__ void __launch_bounds__(128) k_final(const float* __restrict__ ba,
                                               float* __restrict__ out) {
    int b = blockIdx.x >> 1;
    int vo = (blockIdx.x & 1) * 128 + threadIdx.x;
    float s = ba[vo];
#pragma unroll
    for (int cc = 0; cc < 64; cc++) s += g_opart[((size_t)cc * 64 + b) * 256 + vo];
    out[b * 256 + vo] = s;
}

// ---------------- launch --------------------------------------------------
extern "C" void kernel_launch(void* const* d_in, const int* in_sizes, int n_in,
                              void* d_out, int out_size) {
    const float* query = (const float*)d_in[0];
    const float* keys  = (const float*)d_in[1];
    const float* vals  = (const float*)d_in[2];
    const float* rpe   = (const float*)d_in[3];
    const float* Wq    = (const float*)d_in[4];
    const float* bq    = (const float*)d_in[5];
    const float* Wa    = (const float*)d_in[6];
    const float* ba    = (const float*)d_in[7];
    const int*   steps = (const int*)d_in[8];
    float* out = (float*)d_out;

    k_qgemm<<<86, 256>>>(query, Wq, bq, 0);
    k_qgemm<<<85, 256>>>(query, Wq, bq, 86);
    k_qgemm<<<85, 256>>>(query, Wq, bq, 171);
    k_flash<<<dim3(NSC, BATCH), 256>>>(keys, vals, rpe, steps);  // 4th -> profiled
    k_outgemm<<<dim3(64, 8), 256>>>(Wa, steps);
    k_final<<<128, 128>>>(ba, out);
}

// round 14
// speedup vs baseline: 1.1655x; 1.1655x over previous
#include <cuda_runtime.h>
#include <math.h>
#include <string.h>

#define LEN   2048
#define BATCH 64
#define NH    8
#define SCH   64          // scores chunk
#define NSC   32          // # score chunks
#define RCH   128         // read chunk
#define NRC   16          // # read chunks

#define FFMA2(acc, x, y) \
    asm("fma.rn.f32x2 %0, %1, %2, %0;" : "+l"(acc) : "l"(x), "l"(y))
#define PACK2(out, lo, hi) \
    asm("mov.b64 %0, {%1, %2};" : "=l"(out) : "f"(lo), "f"(hi))
#define UNPACK2(lo, hi, in) \
    asm("mov.b64 {%0, %1}, %2;" : "=f"(lo), "=f"(hi) : "l"(in))

// ---------------- scratch (device globals; no allocation) ----------------
__device__ float g_q[BATCH * 2048];              // q[b][h*256+k]
__device__ float g_wexp[NSC * BATCH * SCH * NH]; // exp weights [cc][b][h*64+l]
__device__ float g_mc[NSC * BATCH * NH];         // chunk-local max
__device__ float g_sc[NSC * BATCH * NH];         // chunk-local sum-exp
__device__ float g_rpart[NRC * BATCH * 2048];    // normalized read partials
__device__ float g_opart[128 * BATCH * 256];     // kc partials of out (128 slices)

// ---------------- K1: q GEMM: q = query@Wq + bq ---------------------------
__global__ void __launch_bounds__(256) k_qgemm(const float* __restrict__ query,
                                               const float* __restrict__ Wq,
                                               const float* __restrict__ bq) {
    __shared__ float w_s[32][10];    // [k][j] pad
    __shared__ float q_s[64][33];    // [b][k] pad
    int jt = blockIdx.x;
    int tid = threadIdx.x;
    int b = tid & 63, jg = tid >> 6;
    float acc0 = 0.f, acc1 = 0.f;
    for (int kt = 0; kt < 8; kt++) {
        {   // Wq tile 32k x 8j
            int k = tid >> 3, j = tid & 7;
            w_s[k][j] = Wq[(size_t)(kt * 32 + k) * 2048 + jt * 8 + j];
        }
#pragma unroll
        for (int it = 0; it < 2; it++) {   // query tile 64b x 32k, float4
            int f4 = tid + it * 256;
            int bb = f4 >> 3, k4 = f4 & 7;
            float4 v = ((const float4*)query)[bb * 64 + kt * 8 + k4];
            q_s[bb][k4 * 4 + 0] = v.x;
            q_s[bb][k4 * 4 + 1] = v.y;
            q_s[bb][k4 * 4 + 2] = v.z;
            q_s[bb][k4 * 4 + 3] = v.w;
        }
        __syncthreads();
#pragma unroll
        for (int kk = 0; kk < 32; kk++) {
            float qv = q_s[b][kk];
            acc0 += qv * w_s[kk][jg * 2 + 0];
            acc1 += qv * w_s[kk][jg * 2 + 1];
        }
        __syncthreads();
    }
    int j0 = jt * 8 + jg * 2;
    g_q[b * 2048 + j0 + 0] = acc0 + bq[j0 + 0];
    g_q[b * 2048 + j0 + 1] = acc1 + bq[j0 + 1];
}

// ---------------- K2: scores GEMM, 128 thr, 2 rows/thread -----------------
// grid (32 cc, 64 b), 128 thr. thread = (hp, li): hp = tid>>5, li = tid&31,
// covers rows li and li+32.
__global__ void __launch_bounds__(128) k_scores(const float* __restrict__ keys,
                                                const float* __restrict__ rpe,
                                                const int* __restrict__ steps) {
    int c = blockIdx.x, b = blockIdx.y;
    int lbase = c * SCH;
    int n = steps[b];
    if (lbase >= n) return;
    int nv = n - lbase; if (nv > SCH) nv = SCH;
    int tid = threadIdx.x;

    __shared__ float ks[64][71];                 // keys k-tile, pad 71
    __shared__ unsigned long long q2[4 * 256];   // [hp][k] packed head-pair q
    __shared__ float r_s[SCH];
    __shared__ float s_s[8 * 68];

    // build q2 (coalesced): 8 iters x 128 thr
#pragma unroll
    for (int it = 0; it < 8; it++) {
        int i = it * 128 + tid;
        int hq = i >> 8, k = i & 255;
        float lo = g_q[b * 2048 + (2 * hq) * 256 + k];
        float hi = g_q[b * 2048 + (2 * hq + 1) * 256 + k];
        unsigned long long p;
        PACK2(p, lo, hi);
        q2[hq * 256 + k] = p;
    }
    if (tid < SCH) r_s[tid] = rpe[(lbase + tid) * 64 + b];

    // tile prefetch: 1024 float4 per k-tile, 8 per thread
    float4 buf[8];
    int rowv[8], colv[8];
#pragma unroll
    for (int it = 0; it < 8; it++) {
        int f4 = tid + it * 128;
        int row = f4 >> 4;
        rowv[it] = (row < nv) ? row : (nv - 1);  // clamp: dup load, masked later
        colv[it] = f4 & 15;
    }
#pragma unroll
    for (int it = 0; it < 8; it++)
        buf[it] = ((const float4*)keys)[((size_t)(lbase + rowv[it]) * 64 + b) * 64 + 0 * 16 + colv[it]];

    int hp = tid >> 5, li = tid & 31;
    unsigned long long acc0 = 0ull, acc1 = 0ull;

#pragma unroll
    for (int t = 0; t < 4; t++) {
#pragma unroll
        for (int it = 0; it < 8; it++) {
            int f4 = tid + it * 128;
            int row = f4 >> 4, col = colv[it];
            ks[row][col * 4 + 0] = buf[it].x;
            ks[row][col * 4 + 1] = buf[it].y;
            ks[row][col * 4 + 2] = buf[it].z;
            ks[row][col * 4 + 3] = buf[it].w;
        }
        __syncthreads();
        if (t < 3) {
#pragma unroll
            for (int it = 0; it < 8; it++)
                buf[it] = ((const float4*)keys)[((size_t)(lbase + rowv[it]) * 64 + b) * 64 + (t + 1) * 16 + colv[it]];
        }
        const unsigned long long* qp = q2 + hp * 256 + t * 64;
        const float* kr0 = ks[li];
        const float* kr1 = ks[li + 32];
#pragma unroll
        for (int kk = 0; kk < 64; kk++) {
            unsigned long long qv = qp[kk];
            float kv0 = kr0[kk];
            float kv1 = kr1[kk];
            unsigned long long v0, v1;
            PACK2(v0, kv0, kv0);
            PACK2(v1, kv1, kv1);
            FFMA2(acc0, v0, qv);
            FFMA2(acc1, v1, qv);
        }
        __syncthreads();
    }

    // write rpe-modulated scores (both rows)
    {
        float lo, hi;
        UNPACK2(lo, hi, acc0);
        float r = r_s[li];
        s_s[(2 * hp) * 68 + li]     = lo * r;
        s_s[(2 * hp + 1) * 68 + li] = hi * r;
        UNPACK2(lo, hi, acc1);
        r = r_s[li + 32];
        s_s[(2 * hp) * 68 + li + 32]     = lo * r;
        s_s[(2 * hp + 1) * 68 + li + 32] = hi * r;
    }
    __syncthreads();

    // phase B: 4 warps, each handles 2 heads
    {
        int w = tid >> 5, lane = tid & 31;
#pragma unroll
        for (int hh = 0; hh < 2; hh++) {
            int h = w * 2 + hh;
            float m = -3.0e38f;
            for (int ll = lane; ll < nv; ll += 32) m = fmaxf(m, s_s[h * 68 + ll]);
#pragma unroll
            for (int o = 16; o > 0; o >>= 1) m = fmaxf(m, __shfl_xor_sync(0xffffffffu, m, o));
            float s = 0.f;
            size_t wbase = (size_t)(c * 64 + b) * 512 + h * 64;
            for (int ll = lane; ll < nv; ll += 32) {
                float p = __expf(s_s[h * 68 + ll] - m);
                g_wexp[wbase + ll] = p;
                s += p;
            }
#pragma unroll
            for (int o = 16; o > 0; o >>= 1) s += __shfl_xor_sync(0xffffffffu, s, o);
            if (lane == 0) {
                g_mc[(c * 64 + b) * 8 + h] = m;
                g_sc[(c * 64 + b) * 8 + h] = s;
            }
        }
    }
}

// ---------------- K3: weighted read (f32x2), normalized on the fly --------
// grid (16 cb of 128, 64 b), 256 thr (thread = v)
__global__ void __launch_bounds__(256) k_read(const float* __restrict__ vals,
                                              const int* __restrict__ steps) {
    int cb = blockIdx.x, b = blockIdx.y;
    int lbase = cb * RCH;
    int n = steps[b];
    if (lbase >= n) return;
    int nv = n - lbase; if (nv > RCH) nv = RCH;
    int tid = threadIdx.x;
    int nc_all = (n + SCH - 1) >> 6;

    __shared__ float f_s[8][32];
    __shared__ __align__(16) float w_s[RCH * 8];

    {
        int h = tid >> 5, cc = tid & 31;
        int valid = cc < nc_all;
        float m = valid ? g_mc[(cc * 64 + b) * 8 + h] : -3.0e38f;
        float s = valid ? g_sc[(cc * 64 + b) * 8 + h] : 0.f;
        float M = m;
#pragma unroll
        for (int o = 16; o > 0; o >>= 1) M = fmaxf(M, __shfl_xor_sync(0xffffffffu, M, o));
        float e = __expf(m - M);
        float denom = e * s;
#pragma unroll
        for (int o = 16; o > 0; o >>= 1) denom += __shfl_xor_sync(0xffffffffu, denom, o);
        f_s[h][cc] = e / denom;
    }
    __syncthreads();

    {
        int cc0 = cb * 2;
#pragma unroll
        for (int it = 0; it < 4; it++) {
            int i = tid + it * 256;          // i = h*128 + l
            int h = i >> 7, l = i & 127;
            int cc = cc0 + (l >> 6);
            float wv = g_wexp[(size_t)(cc * 64 + b) * 512 + h * 64 + (l & 63)];
            w_s[l * 8 + h] = wv * f_s[h][cc];
        }
    }
    __syncthreads();

    unsigned long long ah[4];
#pragma unroll
    for (int i = 0; i < 4; i++) ah[i] = 0ull;
    const float* vp = vals + ((size_t)lbase * 64 + b) * 256 + tid;
    const unsigned long long* wll = (const unsigned long long*)w_s;
    int l = 0;
    for (; l + 16 <= nv; l += 16) {
        float v[16];
#pragma unroll
        for (int i = 0; i < 16; i++) v[i] = vp[(size_t)(l + i) * 16384];
#pragma unroll
        for (int i = 0; i < 16; i++) {
            unsigned long long vv;
            PACK2(vv, v[i], v[i]);
#pragma unroll
            for (int hpp = 0; hpp < 4; hpp++)
                FFMA2(ah[hpp], wll[(l + i) * 4 + hpp], vv);
        }
    }
    for (; l < nv; l++) {
        float v = vp[(size_t)l * 16384];
        unsigned long long vv;
        PACK2(vv, v, v);
#pragma unroll
        for (int hpp = 0; hpp < 4; hpp++)
            FFMA2(ah[hpp], wll[l * 4 + hpp], vv);
    }
    size_t pbase = ((size_t)cb * 64 + b) * 2048;
#pragma unroll
    for (int hpp = 0; hpp < 4; hpp++) {
        float lo, hi;
        UNPACK2(lo, hi, ah[hpp]);
        g_rpart[pbase + (hpp * 2 + 0) * 256 + tid] = lo;
        g_rpart[pbase + (hpp * 2 + 1) * 256 + tid] = hi;
    }
}

// ---------------- K4: out GEMM with fused chunk-merge, kc of 16 -----------
// grid (128 kc of 16, 8 bt of 8), 256 thr (thread = vo)
__global__ void __launch_bounds__(256) k_outgemm(const float* __restrict__ Wa,
                                                 const int* __restrict__ steps) {
    int kc = blockIdx.x, bt = blockIdx.y;
    int tid = threadIdx.x;
    __shared__ __align__(16) float R_s[16 * 8];  // [k][bi]
    __shared__ int nc_s[8];
    if (tid < 8) nc_s[tid] = (steps[bt * 8 + tid] + RCH - 1) >> 7;
    __syncthreads();

    if (tid < 128) {   // stage + fused 16-chunk merge: 16 pred loads each
        int bi = tid >> 4, k = tid & 15;
        int b = bt * 8 + bi;
        int nc = nc_s[bi];
        float s = 0.f;
#pragma unroll
        for (int cc = 0; cc < 16; cc++)
            if (cc < nc) s += g_rpart[((size_t)cc * 64 + b) * 2048 + kc * 16 + k];
        R_s[k * 8 + bi] = s;
    }
    __syncthreads();

    unsigned long long acc[4];
#pragma unroll
    for (int p = 0; p < 4; p++) acc[p] = 0ull;
    const unsigned long long* R2 = (const unsigned long long*)R_s;
#pragma unroll
    for (int k = 0; k < 16; k++) {
        float wa = Wa[(size_t)(kc * 16 + k) * 256 + tid];
        unsigned long long wv;
        PACK2(wv, wa, wa);
#pragma unroll
        for (int p = 0; p < 4; p++)
            FFMA2(acc[p], R2[k * 4 + p], wv);
    }
#pragma unroll
    for (int p = 0; p < 4; p++) {
        float lo, hi;
        UNPACK2(lo, hi, acc[p]);
        g_opart[((size_t)kc * 64 + bt * 8 + 2 * p + 0) * 256 + tid] = lo;
        g_opart[((size_t)kc * 64 + bt * 8 + 2 * p + 1) * 256 + tid] = hi;
    }
}

// ---------------- K5: final reduce + bias (128 CTAs x 128 thr) ------------
__global__ void __launch_bounds__(128) k_final(const float* __restrict__ ba,
                                               float* __restrict__ out) {
    int b = blockIdx.x >> 1;
    int vo = (blockIdx.x & 1) * 128 + threadIdx.x;
    float s = ba[vo];
#pragma unroll
    for (int cc = 0; cc < 128; cc++) s += g_opart[((size_t)cc * 64 + b) * 256 + vo];
    out[b * 256 + vo] = s;
}

// ---------------- launch --------------------------------------------------
extern "C" void kernel_launch(void* const* d_in, const int* in_sizes, int n_in,
                              void* d_out, int out_size) {
    const float* query = (const float*)d_in[0];
    const float* keys  = (const float*)d_in[1];
    const float* vals  = (const float*)d_in[2];
    const float* rpe   = (const float*)d_in[3];
    const float* Wq    = (const float*)d_in[4];
    const float* bq    = (const float*)d_in[5];
    const float* Wa    = (const float*)d_in[6];
    const float* ba    = (const float*)d_in[7];
    const int*   steps = (const int*)d_in[8];
    float* out = (float*)d_out;

    k_qgemm<<<256, 256>>>(query, Wq, bq);
    k_scores<<<dim3(NSC, BATCH), 128>>>(keys, rpe, steps);
    k_read<<<dim3(NRC, BATCH), 256>>>(vals, steps);
    k_outgemm<<<dim3(128, 8), 256>>>(Wa, steps);   // 4th -> profiled
    k_final<<<128, 128>>>(ba, out);
}

// round 15
// speedup vs baseline: 1.2336x; 1.0584x over previous
#include <cuda_runtime.h>
#include <math.h>
#include <string.h>

#define LEN   2048
#define BATCH 64
#define NH    8
#define SCH   64          // scores chunk
#define NSC   32          // # score chunks
#define RCH   64          // read chunk (now == SCH)
#define NRC   32          // # read chunks

#define FFMA2(acc, x, y) \
    asm("fma.rn.f32x2 %0, %1, %2, %0;" : "+l"(acc) : "l"(x), "l"(y))
#define PACK2(out, lo, hi) \
    asm("mov.b64 %0, {%1, %2};" : "=l"(out) : "f"(lo), "f"(hi))
#define UNPACK2(lo, hi, in) \
    asm("mov.b64 {%0, %1}, %2;" : "=f"(lo), "=f"(hi) : "l"(in))

// ---------------- scratch (device globals; no allocation) ----------------
__device__ float g_q[BATCH * 2048];              // q[b][h*256+k]
__device__ float g_wexp[NSC * BATCH * SCH * NH]; // exp weights [cc][b][h*64+l]
__device__ float g_mc[NSC * BATCH * NH];         // chunk-local max
__device__ float g_sc[NSC * BATCH * NH];         // chunk-local sum-exp
__device__ float g_rpart[NRC * BATCH * 2048];    // normalized read partials (32 slices)
__device__ float g_opart[64 * BATCH * 256];      // kc partials of out (64 slices)

// ---------------- K1: q GEMM: q = query@Wq + bq ---------------------------
__global__ void __launch_bounds__(256) k_qgemm(const float* __restrict__ query,
                                               const float* __restrict__ Wq,
                                               const float* __restrict__ bq) {
    __shared__ float w_s[32][10];    // [k][j] pad
    __shared__ float q_s[64][33];    // [b][k] pad
    int jt = blockIdx.x;
    int tid = threadIdx.x;
    int b = tid & 63, jg = tid >> 6;
    float acc0 = 0.f, acc1 = 0.f;
    for (int kt = 0; kt < 8; kt++) {
        {   // Wq tile 32k x 8j
            int k = tid >> 3, j = tid & 7;
            w_s[k][j] = Wq[(size_t)(kt * 32 + k) * 2048 + jt * 8 + j];
        }
#pragma unroll
        for (int it = 0; it < 2; it++) {   // query tile 64b x 32k, float4
            int f4 = tid + it * 256;
            int bb = f4 >> 3, k4 = f4 & 7;
            float4 v = ((const float4*)query)[bb * 64 + kt * 8 + k4];
            q_s[bb][k4 * 4 + 0] = v.x;
            q_s[bb][k4 * 4 + 1] = v.y;
            q_s[bb][k4 * 4 + 2] = v.z;
            q_s[bb][k4 * 4 + 3] = v.w;
        }
        __syncthreads();
#pragma unroll
        for (int kk = 0; kk < 32; kk++) {
            float qv = q_s[b][kk];
            acc0 += qv * w_s[kk][jg * 2 + 0];
            acc1 += qv * w_s[kk][jg * 2 + 1];
        }
        __syncthreads();
    }
    int j0 = jt * 8 + jg * 2;
    g_q[b * 2048 + j0 + 0] = acc0 + bq[j0 + 0];
    g_q[b * 2048 + j0 + 1] = acc1 + bq[j0 + 1];
}

// ---------------- K2: scores GEMM, 128 thr, 2 rows/thread -----------------
// grid (32 cc, 64 b), 128 thr. thread = (hp, li): hp = tid>>5, li = tid&31,
// covers rows li and li+32.
__global__ void __launch_bounds__(128) k_scores(const float* __restrict__ keys,
                                                const float* __restrict__ rpe,
                                                const int* __restrict__ steps) {
    int c = blockIdx.x, b = blockIdx.y;
    int lbase = c * SCH;
    int n = steps[b];
    if (lbase >= n) return;
    int nv = n - lbase; if (nv > SCH) nv = SCH;
    int tid = threadIdx.x;

    __shared__ float ks[64][71];                 // keys k-tile, pad 71
    __shared__ unsigned long long q2[4 * 256];   // [hp][k] packed head-pair q
    __shared__ float r_s[SCH];
    __shared__ float s_s[8 * 68];

    // build q2 (coalesced): 8 iters x 128 thr
#pragma unroll
    for (int it = 0; it < 8; it++) {
        int i = it * 128 + tid;
        int hq = i >> 8, k = i & 255;
        float lo = g_q[b * 2048 + (2 * hq) * 256 + k];
        float hi = g_q[b * 2048 + (2 * hq + 1) * 256 + k];
        unsigned long long p;
        PACK2(p, lo, hi);
        q2[hq * 256 + k] = p;
    }
    if (tid < SCH) r_s[tid] = rpe[(lbase + tid) * 64 + b];

    // tile prefetch: 1024 float4 per k-tile, 8 per thread
    float4 buf[8];
    int rowv[8], colv[8];
#pragma unroll
    for (int it = 0; it < 8; it++) {
        int f4 = tid + it * 128;
        int row = f4 >> 4;
        rowv[it] = (row < nv) ? row : (nv - 1);  // clamp: dup load, masked later
        colv[it] = f4 & 15;
    }
#pragma unroll
    for (int it = 0; it < 8; it++)
        buf[it] = ((const float4*)keys)[((size_t)(lbase + rowv[it]) * 64 + b) * 64 + 0 * 16 + colv[it]];

    int hp = tid >> 5, li = tid & 31;
    unsigned long long acc0 = 0ull, acc1 = 0ull;

#pragma unroll
    for (int t = 0; t < 4; t++) {
#pragma unroll
        for (int it = 0; it < 8; it++) {
            int f4 = tid + it * 128;
            int row = f4 >> 4, col = colv[it];
            ks[row][col * 4 + 0] = buf[it].x;
            ks[row][col * 4 + 1] = buf[it].y;
            ks[row][col * 4 + 2] = buf[it].z;
            ks[row][col * 4 + 3] = buf[it].w;
        }
        __syncthreads();
        if (t < 3) {
#pragma unroll
            for (int it = 0; it < 8; it++)
                buf[it] = ((const float4*)keys)[((size_t)(lbase + rowv[it]) * 64 + b) * 64 + (t + 1) * 16 + colv[it]];
        }
        const unsigned long long* qp = q2 + hp * 256 + t * 64;
        const float* kr0 = ks[li];
        const float* kr1 = ks[li + 32];
#pragma unroll
        for (int kk = 0; kk < 64; kk++) {
            unsigned long long qv = qp[kk];
            float kv0 = kr0[kk];
            float kv1 = kr1[kk];
            unsigned long long v0, v1;
            PACK2(v0, kv0, kv0);
            PACK2(v1, kv1, kv1);
            FFMA2(acc0, v0, qv);
            FFMA2(acc1, v1, qv);
        }
        __syncthreads();
    }

    // write rpe-modulated scores (both rows)
    {
        float lo, hi;
        UNPACK2(lo, hi, acc0);
        float r = r_s[li];
        s_s[(2 * hp) * 68 + li]     = lo * r;
        s_s[(2 * hp + 1) * 68 + li] = hi * r;
        UNPACK2(lo, hi, acc1);
        r = r_s[li + 32];
        s_s[(2 * hp) * 68 + li + 32]     = lo * r;
        s_s[(2 * hp + 1) * 68 + li + 32] = hi * r;
    }
    __syncthreads();

    // phase B: 4 warps, each handles 2 heads
    {
        int w = tid >> 5, lane = tid & 31;
#pragma unroll
        for (int hh = 0; hh < 2; hh++) {
            int h = w * 2 + hh;
            float m = -3.0e38f;
            for (int ll = lane; ll < nv; ll += 32) m = fmaxf(m, s_s[h * 68 + ll]);
#pragma unroll
            for (int o = 16; o > 0; o >>= 1) m = fmaxf(m, __shfl_xor_sync(0xffffffffu, m, o));
            float s = 0.f;
            size_t wbase = (size_t)(c * 64 + b) * 512 + h * 64;
            for (int ll = lane; ll < nv; ll += 32) {
                float p = __expf(s_s[h * 68 + ll] - m);
                g_wexp[wbase + ll] = p;
                s += p;
            }
#pragma unroll
            for (int o = 16; o > 0; o >>= 1) s += __shfl_xor_sync(0xffffffffu, s, o);
            if (lane == 0) {
                g_mc[(c * 64 + b) * 8 + h] = m;
                g_sc[(c * 64 + b) * 8 + h] = s;
            }
        }
    }
}

// ---------------- K3: weighted read, v-pair threads, chunk=64 -------------
// grid (32 cb of 64, 64 b), 128 thr: thread owns v-pair (2tid, 2tid+1)
__global__ void __launch_bounds__(128) k_read(const float* __restrict__ vals,
                                              const int* __restrict__ steps) {
    int cb = blockIdx.x, b = blockIdx.y;
    int lbase = cb * RCH;
    int n = steps[b];
    if (lbase >= n) return;
    int nv = n - lbase; if (nv > RCH) nv = RCH;
    int tid = threadIdx.x;
    int nc_all = (n + SCH - 1) >> 6;

    __shared__ float f_s[8][32];                             // merge factor [h][cc]
    __shared__ __align__(16) unsigned long long w2[RCH * 8]; // splat weights [l][h]

    // ---- factors: 4 warps; warp wi handles heads 2wi, 2wi+1 ----
    {
        int wi = tid >> 5, lane = tid & 31;
#pragma unroll
        for (int hh = 0; hh < 2; hh++) {
            int h = wi * 2 + hh;
            int valid = lane < nc_all;
            float m = valid ? g_mc[(lane * 64 + b) * 8 + h] : -3.0e38f;
            float s = valid ? g_sc[(lane * 64 + b) * 8 + h] : 0.f;
            float M = m;
#pragma unroll
            for (int o = 16; o > 0; o >>= 1) M = fmaxf(M, __shfl_xor_sync(0xffffffffu, M, o));
            float e = __expf(m - M);
            float denom = e * s;
#pragma unroll
            for (int o = 16; o > 0; o >>= 1) denom += __shfl_xor_sync(0xffffffffu, denom, o);
            f_s[h][lane] = e / denom;
        }
    }
    __syncthreads();

    // ---- stage splat weights (this CTA's chunk only); zero for l >= nv ----
    {
#pragma unroll
        for (int it = 0; it < 4; it++) {
            int i = tid + it * 128;          // i = h*64 + l
            int h = i >> 6, l = i & 63;
            float wv = 0.f;
            if (l < nv)
                wv = g_wexp[(size_t)(cb * 64 + b) * 512 + h * 64 + l] * f_s[h][cb];
            unsigned long long p;
            PACK2(p, wv, wv);
            w2[l * 8 + h] = p;
        }
    }
    __syncthreads();

    // ---- stream vals: thread owns v-pair; weights already packed ----
    unsigned long long acc[8];
#pragma unroll
    for (int h = 0; h < 8; h++) acc[h] = 0ull;
    const unsigned long long* vp =
        ((const unsigned long long*)(vals + ((size_t)lbase * 64 + b) * 256)) + tid;
    for (int l0 = 0; l0 < nv; l0 += 8) {
        unsigned long long v[8];
#pragma unroll
        for (int i = 0; i < 8; i++) v[i] = vp[(size_t)(l0 + i) * 8192];
#pragma unroll
        for (int i = 0; i < 8; i++) {
            const unsigned long long* wr = w2 + (l0 + i) * 8;
#pragma unroll
            for (int h = 0; h < 8; h++)
                FFMA2(acc[h], wr[h], v[i]);
        }
    }
    size_t pbase = ((size_t)cb * 64 + b) * 2048;
#pragma unroll
    for (int h = 0; h < 8; h++) {
        float lo, hi;
        UNPACK2(lo, hi, acc[h]);
        ((float2*)(g_rpart + pbase + h * 256))[tid] = make_float2(lo, hi);
    }
}

// ---------------- K4: out GEMM with fused chunk-merge, kc of 32 -----------
// grid (64 kc of 32, 8 bt of 8), 256 thr (thread = vo)
__global__ void __launch_bounds__(256) k_outgemm(const float* __restrict__ Wa,
                                                 const int* __restrict__ steps) {
    int kc = blockIdx.x, bt = blockIdx.y;
    int tid = threadIdx.x;
    __shared__ __align__(16) float R_s[32 * 8];  // [k][bi]
    __shared__ int nc_s[8];
    if (tid < 8) nc_s[tid] = (steps[bt * 8 + tid] + RCH - 1) >> 6;
    __syncthreads();

    {   // stage + fused 32-chunk merge: 1 elem per thread, 32 pred loads
        int bi = tid >> 5, k = tid & 31;
        int b = bt * 8 + bi;
        int nc = nc_s[bi];
        float s = 0.f;
#pragma unroll
        for (int cc = 0; cc < 32; cc++)
            if (cc < nc) s += g_rpart[((size_t)cc * 64 + b) * 2048 + kc * 32 + k];
        R_s[k * 8 + bi] = s;
    }
    __syncthreads();

    unsigned long long acc[4];
#pragma unroll
    for (int p = 0; p < 4; p++) acc[p] = 0ull;
    const unsigned long long* R2 = (const unsigned long long*)R_s;
#pragma unroll 8
    for (int k = 0; k < 32; k++) {
        float wa = Wa[(size_t)(kc * 32 + k) * 256 + tid];
        unsigned long long wv;
        PACK2(wv, wa, wa);
#pragma unroll
        for (int p = 0; p < 4; p++)
            FFMA2(acc[p], R2[k * 4 + p], wv);
    }
#pragma unroll
    for (int p = 0; p < 4; p++) {
        float lo, hi;
        UNPACK2(lo, hi, acc[p]);
        g_opart[((size_t)kc * 64 + bt * 8 + 2 * p + 0) * 256 + tid] = lo;
        g_opart[((size_t)kc * 64 + bt * 8 + 2 * p + 1) * 256 + tid] = hi;
    }
}

// ---------------- K5: final reduce + bias (128 CTAs x 128 thr) ------------
__global__ void __launch_bounds__(128) k_final(const float* __restrict__ ba,
                                               float* __restrict__ out) {
    int b = blockIdx.x >> 1;
    int vo = (blockIdx.x & 1) * 128 + threadIdx.x;
    float s = ba[vo];
#pragma unroll
    for (int cc = 0; cc < 64; cc++) s += g_opart[((size_t)cc * 64 + b) * 256 + vo];
    out[b * 256 + vo] = s;
}

// ---------------- launch --------------------------------------------------
extern "C" void kernel_launch(void* const* d_in, const int* in_sizes, int n_in,
                              void* d_out, int out_size) {
    const float* query = (const float*)d_in[0];
    const float* keys  = (const float*)d_in[1];
    const float* vals  = (const float*)d_in[2];
    const float* rpe   = (const float*)d_in[3];
    const float* Wq    = (const float*)d_in[4];
    const float* bq    = (const float*)d_in[5];
    const float* Wa    = (const float*)d_in[6];
    const float* ba    = (const float*)d_in[7];
    const int*   steps = (const int*)d_in[8];
    float* out = (float*)d_out;

    k_qgemm<<<256, 256>>>(query, Wq, bq);
    k_scores<<<dim3(NSC, BATCH), 128>>>(keys, rpe, steps);
    k_read<<<dim3(NRC, BATCH), 128>>>(vals, steps);
    k_outgemm<<<dim3(64, 8), 256>>>(Wa, steps);    // 4th -> profiled
    k_final<<<128, 128>>>(ba, out);
}